// round 14
// baseline (speedup 1.0000x reference)
#include <cuda_runtime.h>
#include <cstdint>

// FlowNetC correlation: B=4, C=128, H=W=96, md=20, stride2=2, K=1, S1=1.
// out[b, iy*21+ix, y, x] = (1/128)*sum_c in1[b,c,y,x]*in2[b,c,y+dy,x+dx]
// dy=(iy-10)*2, dx=(ix-10)*2, zero outside [0,96).
//
// Thread tile: 7 dx x 12 x (42 f32x2 accs). K stored twice (copy B = elems
// shifted left 2) so every dxg's 24-float window is float4-aligned ->
// 6 LDS.128 k + 3 LDS.128 q per channel, all at the crossbar wavefront floor
// (KROW == 4 mod 32 words spreads dyg rows; 3xg mod 8 spreads xg lanes).

#define ND 21
#define NDD 441
#define CH 128
#define HH 96
#define WW 96
#define DYG 7
#define CCK 8
#define NCHUNK 16
#define QSTP 100
#define KX 144                 // K row: [0..19]=0, [20..115]=data, rest 0
#define KROW 1156              // 8*KX + 4 ; == 4 mod 32 words, /4 == 1 mod 8
#define ABASE 832              // copy A base (word-aligned to 32)
#define BBASE 8924             // = ABASE + 7*KROW  (== 0 mod 4)
#define SMEMF (BBASE + DYG*KROW)   // 17016 floats
#define SMEMB (SMEMF*4)            // 68064 B -> 2 blocks/SM
#define NT 192
#define NACT 168               // 3 dxg * 7 dyg * 8 xg

typedef unsigned long long u64;

__device__ __forceinline__ u64 ffma2(u64 a, u64 b, u64 c) {
    u64 d;
    asm("fma.rn.f32x2 %0, %1, %2, %3;" : "=l"(d) : "l"(a), "l"(b), "l"(c));
    return d;
}

__global__ void __launch_bounds__(NT, 2)
corr_kernel(const float* __restrict__ in1, const float* __restrict__ in2,
            float* __restrict__ out)
{
    extern __shared__ float smem[];
    float* Qs  = smem;               // [8][QSTP]
    float* KsA = smem + ABASE;       // [7][8][KX]
    float* KsB = smem + BBASE;       // same rows, B[l] = elem(l+2)

    const int y   = blockIdx.x;
    const int b   = blockIdx.y;
    const int p   = blockIdx.z;      // dy rows p*7 .. p*7+6
    const int tid = threadIdx.x;

    // Zero both K copies once (logical pads stay zero; interior rewritten)
    for (int i = tid; i < (SMEMF - ABASE) / 4; i += NT)
        *(float4*)(smem + ABASE + 4 * i) = make_float4(0.f, 0.f, 0.f, 0.f);

    // Tile mapping: dxg outer, dyg mid, xg inner
    const bool active = tid < NACT;
    int dxg = 0, dyg = 0, xg = 0;
    if (active) {
        dxg = tid / 56;
        int r = tid - dxg * 56;
        dyg = r / 8;
        xg  = r - dyg * 8;
    }
    const int x0 = 12 * xg;
    // window base (elements): koff = 12*xg + 14*dxg. float4-aligned source:
    //   dxg 0: A + koff      (koff%4==0)
    //   dxg 1: B + koff - 2  (B[l]=elem l+2; koff-2 %4==0)
    //   dxg 2: A + koff      (28 %4==0)
    const float* kbase = (dxg == 1 ? (KsB + 12 * xg + 12) : (KsA + 12 * xg + 14 * dxg))
                       + dyg * KROW;
    const float* qbase = Qs + x0;

    u64 acc2[7][6];
    #pragma unroll
    for (int j = 0; j < 7; ++j)
        #pragma unroll
        for (int n = 0; n < 6; ++n) acc2[j][n] = 0ull;

    for (int cc = 0; cc < NCHUNK; ++cc) {
        __syncthreads();   // previous chunk fully consumed
        // ---- Load: 192 Q float4 + 1344 K float4 tasks (K -> A and B copies) ----
        #pragma unroll
        for (int it = 0; it < 8; ++it) {
            int i = tid + it * NT;
            if (it == 0) {                      // i < 192: Q tasks
                int c  = i / 24;
                int xq = i - c * 24;
                float4 v = *(const float4*)(in1 +
                    (((size_t)b * CH + cc * CCK + c) * HH + y) * WW + 4 * xq);
                *(float4*)(Qs + c * QSTP + 4 * xq) = v;
            } else {
                int t   = i - NT;
                int r   = t / 192;
                int rem = t - r * 192;
                int c   = rem / 24;
                int xq  = rem - c * 24;
                int yy  = y + (p * DYG + r - 10) * 2;
                float4 v = make_float4(0.f, 0.f, 0.f, 0.f);
                if ((unsigned)yy < HH)
                    v = *(const float4*)(in2 +
                        (((size_t)b * CH + cc * CCK + c) * HH + yy) * WW + 4 * xq);
                int e = 20 + 4 * xq;
                float* ra = KsA + r * KROW + c * KX;
                float* rb = KsB + r * KROW + c * KX;
                *(float4*)(ra + e) = v;
                *(float2*)(rb + e - 2) = make_float2(v.x, v.y);  // B[e-2]=elem e
                *(float2*)(rb + e)     = make_float2(v.z, v.w);  // B[e]  =elem e+2
            }
        }
        __syncthreads();

        if (active) {
            #pragma unroll 1
            for (int c = 0; c < CCK; ++c) {
                const float* qp = qbase + c * QSTP;
                const float* kp = kbase + c * KX;
                u64 q2[6], k2[12];
                #pragma unroll
                for (int t = 0; t < 3; ++t) {
                    ulonglong2 v = *(const ulonglong2*)(qp + 4 * t);
                    q2[2 * t] = v.x; q2[2 * t + 1] = v.y;
                }
                #pragma unroll
                for (int t = 0; t < 6; ++t) {
                    ulonglong2 v = *(const ulonglong2*)(kp + 4 * t);
                    k2[2 * t] = v.x; k2[2 * t + 1] = v.y;
                }
                #pragma unroll
                for (int j = 0; j < 7; ++j)
                    #pragma unroll
                    for (int n = 0; n < 6; ++n)
                        acc2[j][n] = ffma2(q2[n], k2[n + j], acc2[j][n]);
            }
        }
    }

    if (active) {
        const int diy = p * DYG + dyg;
        const float s = 1.0f / 128.0f;
        #pragma unroll
        for (int j = 0; j < 7; ++j) {
            int d = diy * ND + dxg * 7 + j;
            float* o = out + (((size_t)b * NDD + d) * HH + y) * WW + x0;
            #pragma unroll
            for (int m = 0; m < 3; ++m) {
                float2 a0 = *(float2*)&acc2[j][2 * m];
                float2 a1 = *(float2*)&acc2[j][2 * m + 1];
                *(float4*)(o + 4 * m) =
                    make_float4(a0.x * s, a0.y * s, a1.x * s, a1.y * s);
            }
        }
    }
}

extern "C" void kernel_launch(void* const* d_in, const int* in_sizes, int n_in,
                              void* d_out, int out_size)
{
    const float* in1 = (const float*)d_in[0];
    const float* in2 = (const float*)d_in[1];
    float* out = (float*)d_out;

    cudaFuncSetAttribute(corr_kernel,
                         cudaFuncAttributeMaxDynamicSharedMemorySize, SMEMB);
    corr_kernel<<<dim3(HH, 4, 3), NT, SMEMB>>>(in1, in2, out);
}

// round 15
// speedup vs baseline: 1.0427x; 1.0427x over previous
#include <cuda_runtime.h>
#include <cstdint>

// FlowNetC correlation: B=4, C=128, H=W=96, md=20, stride2=2, K=1, S1=1.
// out[b, iy*21+ix, y, x] = (1/128)*sum_c in1[b,c,y,x]*in2[b,c,y+dy,x+dx]
// dy=(iy-10)*2, dx=(ix-10)*2, zero outside [0,96).
//
// Compute: 7dx x 12x register tile, k LDS.64 at the 2-wavefront floor
// (KROW == 2 mod 32 words; dxg-outer warp mapping). Loading: 4-deep
// cp.async pipeline, 4-channel chunks, one __syncthreads per chunk.

#define ND 21
#define NDD 441
#define CH 128
#define HH 96
#define WW 96
#define CCK 4                 // channels per chunk
#define NCHUNK 32
#define QSTP 100
#define KX 144                // K row: [0..19]=0, [20..115]=data, rest 0
#define KROW 578              // 4*KX + 2 ; == 2 mod 32 words (bank-class split)
#define KBASE 416             // K offset inside buffer (floats), == 0 mod 32
#define BUFF 4480             // floats per buffer (Q 416 + K 4046, padded)
#define BUFFB (BUFF*4)        // 17920 bytes
#define NBUF 4
#define SMEMB (NBUF*BUFFB)    // 71680 B -> 2 blocks/SM
#define NT 192
#define NACT 168              // 3 dxg * 7 dyg * 8 xg
#define CHADV ((size_t)CCK*HH*WW)   // gmem float advance per chunk

typedef unsigned long long u64;

__device__ __forceinline__ u64 ffma2(u64 a, u64 b, u64 c) {
    u64 d;
    asm("fma.rn.f32x2 %0, %1, %2, %3;" : "=l"(d) : "l"(a), "l"(b), "l"(c));
    return d;
}
__device__ __forceinline__ uint32_t smem_u32(const void* p) {
    uint32_t a;
    asm("{ .reg .u64 t; cvta.to.shared.u64 t, %1; cvt.u32.u64 %0, t; }"
        : "=r"(a) : "l"(p));
    return a;
}
__device__ __forceinline__ void cpa16(uint32_t d, const void* s) {
    asm volatile("cp.async.cg.shared.global [%0], [%1], 16;"
                 :: "r"(d), "l"(s) : "memory");
}
__device__ __forceinline__ void cpa8(uint32_t d, const void* s, int sz) {
    asm volatile("cp.async.ca.shared.global [%0], [%1], 8, %2;"
                 :: "r"(d), "l"(s), "r"(sz) : "memory");
}
#define CP_COMMIT() asm volatile("cp.async.commit_group;" ::: "memory")
template <int N>
__device__ __forceinline__ void cp_wait() {
    asm volatile("cp.async.wait_group %0;" :: "n"(N) : "memory");
}

__global__ void __launch_bounds__(NT, 2)
corr_kernel(const float* __restrict__ in1, const float* __restrict__ in2,
            float* __restrict__ out)
{
    extern __shared__ float smem[];
    const uint32_t smb = smem_u32(smem);
    const int y   = blockIdx.x;
    const int b   = blockIdx.y;
    const int p   = blockIdx.z;        // dy rows p*7 .. p*7+6
    const int tid = threadIdx.x;

    // Zero all buffers' K regions once (pads must stay zero), then barrier
    // so no cp.async can race the zero-stores.
    for (int i = tid; i < NBUF * BUFF / 4; i += NT)
        *(float4*)(smem + 4 * i) = make_float4(0.f, 0.f, 0.f, 0.f);

    // ---- loader slots: 4 per thread (Q: tid<96 slot0; K: 672 tasks) ----
    const float* gsrc[4];
    uint32_t     soff[4];
    int          ksz[4];
    const bool isQ = tid < 96;
    #pragma unroll
    for (int s = 0; s < 4; ++s) {
        if (s == 0 && isQ) {
            int c0 = tid / 24, xq = tid - c0 * 24;
            gsrc[0] = in1 + (((size_t)b * CH + c0) * HH + y) * WW + 4 * xq;
            soff[0] = (uint32_t)(c0 * QSTP + 4 * xq) * 4u;
            ksz[0]  = 16;
        } else {
            int t = (s == 0) ? (tid - 96) : (tid - 96 + 192 * s);
            int r = t / 96, rem = t - r * 96;
            int c = rem / 24, xq = rem - c * 24;
            int yy = y + (p * 7 + r - 10) * 2;
            int ok = ((unsigned)yy < HH);
            int yc = ok ? yy : 0;
            gsrc[s] = in2 + (((size_t)b * CH + c) * HH + yc) * WW + 4 * xq;
            soff[s] = (uint32_t)(KBASE + r * KROW + c * KX + 20 + 4 * xq) * 4u;
            ksz[s]  = ok ? 8 : 0;
        }
    }

#define ISSUE(CC) do {                                                       \
        uint32_t base_ = smb + ((CC) & 3) * BUFFB;                           \
        const size_t ga_ = (size_t)(CC) * CHADV;                             \
        if (isQ) cpa16(base_ + soff[0], gsrc[0] + ga_);                      \
        else { cpa8(base_ + soff[0], gsrc[0] + ga_, ksz[0]);                 \
               cpa8(base_ + soff[0] + 8, gsrc[0] + ga_ + 2, ksz[0]); }       \
        _Pragma("unroll")                                                    \
        for (int s_ = 1; s_ < 4; ++s_) {                                     \
            cpa8(base_ + soff[s_], gsrc[s_] + ga_, ksz[s_]);                 \
            cpa8(base_ + soff[s_] + 8, gsrc[s_] + ga_ + 2, ksz[s_]);         \
        }                                                                    \
        CP_COMMIT();                                                         \
    } while (0)

    __syncthreads();          // zero-stores visible before any cp.async lands
    ISSUE(0);
    ISSUE(1);

    // ---- compute tile: dxg outer, dyg mid, xg inner ----
    const bool active = tid < NACT;
    int dxg = 0, dyg = 0, xg = 0;
    if (active) {
        dxg = tid / 56;
        int r = tid - dxg * 56;
        dyg = r / 8;
        xg  = r - dyg * 8;
    }
    const int x0    = 12 * xg;
    const int kbo   = KBASE + dyg * KROW + 12 * xg + 14 * dxg;  // window base
    u64 acc2[7][6];
    #pragma unroll
    for (int j = 0; j < 7; ++j)
        #pragma unroll
        for (int n = 0; n < 6; ++n) acc2[j][n] = 0ull;

    #pragma unroll 1
    for (int cc = 0; cc < NCHUNK; ++cc) {
        if (cc + 2 < NCHUNK) { ISSUE(cc + 2); cp_wait<2>(); }
        else if (cc + 2 == NCHUNK) cp_wait<1>();
        else cp_wait<0>();
        __syncthreads();       // chunk cc globally visible; buf (cc+2)&3 free

        if (active) {
            const float* buf = smem + (cc & 3) * BUFF;
            #pragma unroll 1
            for (int c = 0; c < CCK; ++c) {
                const float* qp = buf + c * QSTP + x0;
                const float* kp = buf + kbo + c * KX;
                u64 q2[6], k2[12];
                #pragma unroll
                for (int t = 0; t < 3; ++t) {
                    ulonglong2 v = *(const ulonglong2*)(qp + 4 * t);
                    q2[2 * t] = v.x; q2[2 * t + 1] = v.y;
                }
                #pragma unroll
                for (int t = 0; t < 12; ++t)
                    k2[t] = *(const u64*)(kp + 2 * t);
                #pragma unroll
                for (int j = 0; j < 7; ++j)
                    #pragma unroll
                    for (int n = 0; n < 6; ++n)
                        acc2[j][n] = ffma2(q2[n], k2[n + j], acc2[j][n]);
            }
        }
    }

    if (active) {
        const int diy = p * 7 + dyg;
        const float s = 1.0f / 128.0f;
        #pragma unroll
        for (int j = 0; j < 7; ++j) {
            int d = diy * ND + dxg * 7 + j;
            float* o = out + (((size_t)b * NDD + d) * HH + y) * WW + x0;
            #pragma unroll
            for (int m = 0; m < 3; ++m) {
                float2 a0 = *(float2*)&acc2[j][2 * m];
                float2 a1 = *(float2*)&acc2[j][2 * m + 1];
                *(float4*)(o + 4 * m) =
                    make_float4(a0.x * s, a0.y * s, a1.x * s, a1.y * s);
            }
        }
    }
}

extern "C" void kernel_launch(void* const* d_in, const int* in_sizes, int n_in,
                              void* d_out, int out_size)
{
    const float* in1 = (const float*)d_in[0];
    const float* in2 = (const float*)d_in[1];
    float* out = (float*)d_out;

    cudaFuncSetAttribute(corr_kernel,
                         cudaFuncAttributeMaxDynamicSharedMemorySize, SMEMB);
    corr_kernel<<<dim3(HH, 4, 3), NT, SMEMB>>>(in1, in2, out);
}